// round 2
// baseline (speedup 1.0000x reference)
#include <cuda_runtime.h>
#include <math.h>

// Problem constants (B=8, N=180, T=256, L=16, H=64, S=240)
#define BB  8
#define NN  180
#define TT  256
#define LL  16
#define HH  64
#define SSW 240
#define K1  60
#define K2  20
#define FF  192

// ---------------- scratch (__device__ globals; no allocation) ----------------
__device__ float d_hs[BB*NN*HH];     // sum_s h * (1/x)
__device__ float d_r[BB*NN];         // sum_s 1/x
__device__ float d_G[BB*NN*NN];      // graph (b, j, n)
__device__ float d_Ne1[BB*NN*HH];
__device__ float d_row1[BB*NN];
__device__ float d_col1[BB*NN];
__device__ float d_M1[BB*NN*HH];
__device__ float d_P1[BB*NN*HH];
__device__ float d_H1[BB*NN*FF];
__device__ float d_topv1[BB*K1];
__device__ int   d_topi1[BB*K1];
__device__ float d_Hg1[BB*K1*FF];
__device__ float d_G1[BB*K1*K1];
__device__ float d_Ne2[BB*K1*HH];
__device__ float d_row2[BB*K1];
__device__ float d_col2[BB*K1];
__device__ float d_M2[BB*K1*HH];
__device__ float d_P2[BB*K1*HH];
__device__ float d_H2[BB*K1*FF];
__device__ float d_topv2[BB*K2];
__device__ int   d_topi2[BB*K2];

__device__ __forceinline__ float sigf(float x) {
    return __fdividef(1.0f, 1.0f + __expf(-x));
}
__device__ __forceinline__ float tanh_f(float x) {
    return 1.0f - __fdividef(2.0f, __expf(2.0f * x) + 1.0f);
}

// ---------------- K1: windowed LSTM-cell reduction --------------------------
// One block per (n, b). Computes hs[b,n,:] and r[b,n].
// gates: ig=rows[0:64), gg=rows[128:192), og=rows[192:256) of W_ih[n] (fg unused).
__global__ void lstm_kernel(const float* __restrict__ x,
                            const float* __restrict__ W_ih,
                            const float* __restrict__ b_ih,
                            const float* __restrict__ b_hh) {
    int n = blockIdx.x >> 3;
    int b = blockIdx.x & 7;
    __shared__ float sx[TT];
    __shared__ float sinv[SSW + 16];   // padded so tree reduction can read zeros
    __shared__ float sp[256];

    int tid = threadIdx.x;
    const float* xp = x + (b * NN + n) * TT;
    sx[tid] = xp[tid];
    if (tid < 16) sinv[SSW + tid] = 0.0f;
    __syncthreads();
    if (tid < SSW) {
        sinv[tid] = __fdividef(1.0f, sx[LL + tid]);
    }

    int h = tid & 63;
    const float* Wn = W_ih + n * 256 * LL;
    float w0[LL], w1[LL], w2[LL];
#pragma unroll
    for (int l = 0; l < LL; l++) {
        w0[l] = Wn[h * LL + l];
        w1[l] = Wn[(128 + h) * LL + l];
        w2[l] = Wn[(192 + h) * LL + l];
    }
    float bi0 = b_ih[n * 256 + h]       + b_hh[n * 256 + h];
    float bi1 = b_ih[n * 256 + 128 + h] + b_hh[n * 256 + 128 + h];
    float bi2 = b_ih[n * 256 + 192 + h] + b_hh[n * 256 + 192 + h];
    __syncthreads();

    float acc = 0.0f;
    int s0 = tid >> 6;                 // 4 s-lanes per h
    for (int i = 0; i < SSW / 4; i++) {
        int s = s0 + 4 * i;
        float ig = bi0, gg = bi1, og = bi2;
#pragma unroll
        for (int l = 0; l < LL; l++) {
            float xv = sx[s + l];
            ig = fmaf(w0[l], xv, ig);
            gg = fmaf(w1[l], xv, gg);
            og = fmaf(w2[l], xv, og);
        }
        float c  = sigf(ig) * tanh_f(gg);
        float hv = sigf(og) * tanh_f(c);
        acc = fmaf(hv, sinv[s], acc);
    }
    sp[tid] = acc;
    __syncthreads();
    if (tid < HH) {
        d_hs[(b * NN + n) * HH + tid] = sp[tid] + sp[tid + 64] + sp[tid + 128] + sp[tid + 192];
    }
    // deterministic reduction of sinv[0:240) (padded with zeros to 256)
    if (tid < 128) sp[tid] = sinv[tid] + sinv[tid + 128];
    __syncthreads();
    if (tid < 64) sp[tid] += sp[tid + 64];
    __syncthreads();
    if (tid < 32) {
        float v = sp[tid] + sp[tid + 32];
#pragma unroll
        for (int off = 16; off > 0; off >>= 1)
            v += __shfl_down_sync(0xffffffffu, v, off);
        if (tid == 0) d_r[b * NN + n] = v;
    }
}

// ---------------- K2: G[b,j,n] = (W_fc[n,j]·hs[b,n] + b_fc[n,j]*r[b,n]) / S --
// One block per n; each thread handles one j for all 8 batches (W_fc read once).
__global__ void gmat_kernel(const float* __restrict__ W_fc,
                            const float* __restrict__ b_fc) {
    int n = blockIdx.x;
    __shared__ float sh[BB * HH];
    __shared__ float srr[BB];
    int tid = threadIdx.x;
    for (int t = tid; t < BB * HH; t += 192) {
        int b = t >> 6;
        sh[t] = d_hs[(b * NN + n) * HH + (t & 63)];
    }
    if (tid < BB) srr[tid] = d_r[tid * NN + n];
    __syncthreads();

    for (int j = tid; j < NN; j += 192) {
        const float* w = W_fc + (n * NN + j) * HH;
        float bfc = b_fc[n * NN + j];
        float acc[BB];
#pragma unroll
        for (int b = 0; b < BB; b++) acc[b] = bfc * srr[b];
#pragma unroll 16
        for (int hh = 0; hh < HH; hh++) {
            float wv = w[hh];
#pragma unroll
            for (int b = 0; b < BB; b++) acc[b] = fmaf(wv, sh[b * HH + hh], acc[b]);
        }
#pragma unroll
        for (int b = 0; b < BB; b++)
            d_G[(b * NN + j) * NN + n] = acc[b] * (1.0f / (float)SSW);
    }
}

// ---------------- generic bodies --------------------------------------------
// Ne = X(B,Nn,F) @ W(F,64); one block per (b,n); 64 threads.
__device__ __forceinline__ void ne_body(const float* __restrict__ X,
                                        const float* __restrict__ W,
                                        float* __restrict__ Ne, int F) {
    __shared__ float sx[256];
    int bn = blockIdx.x, tid = threadIdx.x;
    for (int t = tid; t < F; t += 64) sx[t] = X[bn * F + t];
    __syncthreads();
    float acc = 0.0f;
    for (int t = 0; t < F; t++) acc = fmaf(sx[t], W[t * HH + tid], acc);
    Ne[bn * HH + tid] = acc;
}

__device__ __forceinline__ void rowcol_body(const float* __restrict__ G,
                                            float* __restrict__ row,
                                            float* __restrict__ col, int Nn) {
    int b = blockIdx.x, tid = threadIdx.x;
    if (tid < Nn) {
        float r = 0.0f, c = 0.0f;
        for (int j = 0; j < Nn; j++) {
            r += G[(b * Nn + tid) * Nn + j];
            c += G[(b * Nn + j) * Nn + tid];
        }
        row[b * Nn + tid] = r;
        col[b * Nn + tid] = c;
    }
}

// M = G@Ne, P = G^T@Ne. One block per (b, 4-row tile); 64 threads (o).
__device__ __forceinline__ void mp_body(const float* __restrict__ G,
                                        const float* __restrict__ Ne,
                                        float* __restrict__ M,
                                        float* __restrict__ P, int Nn) {
    __shared__ float srow[4 * NN];
    __shared__ float scol[4 * NN];
    int nt = Nn / 4;
    int bt = blockIdx.x;
    int b = bt / nt;
    int it = (bt - b * nt) * 4;
    int tid = threadIdx.x;
    for (int idx = tid; idx < 4 * Nn; idx += 64) {
        int ii = idx / Nn, k = idx - ii * Nn, i = it + ii;
        srow[ii * NN + k] = G[(b * Nn + i) * Nn + k];
        scol[ii * NN + k] = G[(b * Nn + k) * Nn + i];
    }
    __syncthreads();
    float m[4] = {0, 0, 0, 0}, p[4] = {0, 0, 0, 0};
    for (int k = 0; k < Nn; k++) {
        float ne = Ne[(b * Nn + k) * HH + tid];
#pragma unroll
        for (int ii = 0; ii < 4; ii++) {
            m[ii] = fmaf(srow[ii * NN + k], ne, m[ii]);
            p[ii] = fmaf(scol[ii * NN + k], ne, p[ii]);
        }
    }
#pragma unroll
    for (int ii = 0; ii < 4; ii++) {
        int i = it + ii;
        M[(b * Nn + i) * HH + tid] = m[ii];
        P[(b * Nn + i) * HH + tid] = p[ii];
    }
}

// H = [relu(0.5(M+P)) | relu((G/row)^T @ M) | relu((G./col) @ P)]
__device__ __forceinline__ void hcat_body(const float* __restrict__ G,
                                          const float* __restrict__ M,
                                          const float* __restrict__ P,
                                          const float* __restrict__ row,
                                          const float* __restrict__ col,
                                          float* __restrict__ Hout, int Nn) {
    __shared__ float sa[4 * NN];
    __shared__ float sc[4 * NN];
    int nt = Nn / 4;
    int bt = blockIdx.x;
    int b = bt / nt;
    int it = (bt - b * nt) * 4;
    int tid = threadIdx.x;
    for (int idx = tid; idx < 4 * Nn; idx += 64) {
        int ii = idx / Nn, k = idx - ii * Nn, i = it + ii;
        sa[ii * NN + k] = G[(b * Nn + k) * Nn + i] / row[b * Nn + k];
        sc[ii * NN + k] = G[(b * Nn + i) * Nn + k] / col[b * Nn + k];
    }
    __syncthreads();
    float a2[4] = {0, 0, 0, 0}, a3[4] = {0, 0, 0, 0};
    for (int k = 0; k < Nn; k++) {
        float m = M[(b * Nn + k) * HH + tid];
        float p = P[(b * Nn + k) * HH + tid];
#pragma unroll
        for (int ii = 0; ii < 4; ii++) {
            a2[ii] = fmaf(sa[ii * NN + k], m, a2[ii]);
            a3[ii] = fmaf(sc[ii * NN + k], p, a3[ii]);
        }
    }
#pragma unroll
    for (int ii = 0; ii < 4; ii++) {
        int i = it + ii;
        float m0 = M[(b * Nn + i) * HH + tid];
        float p0 = P[(b * Nn + i) * HH + tid];
        float* hp = Hout + (b * Nn + i) * FF + tid;
        hp[0]      = fmaxf(0.0f, 0.5f * (m0 + p0));
        hp[HH]     = fmaxf(0.0f, a2[ii]);
        hp[2 * HH] = fmaxf(0.0f, a3[ii]);
    }
}

// top-k by rank counting (exact jax top_k order, stable tie-break)
__device__ __forceinline__ void topk_body(const float* __restrict__ Hf,
                                          const float* __restrict__ w,
                                          float* __restrict__ topv,
                                          int* __restrict__ topi, int Nn, int k) {
    __shared__ float ss[NN];
    __shared__ float srn;
    int b = blockIdx.x, tid = threadIdx.x;
    if (tid == 0) {
        float s = 0.0f;
        for (int f = 0; f < FF; f++) s += w[f] * w[f];
        srn = rsqrtf(s);
    }
    __syncthreads();
    if (tid < Nn) {
        const float* hp = Hf + (b * Nn + tid) * FF;
        float acc = 0.0f;
        for (int f = 0; f < FF; f++) acc = fmaf(hp[f], w[f], acc);
        ss[tid] = acc * srn;
    }
    __syncthreads();
    if (tid < Nn) {
        float v = ss[tid];
        int cnt = 0;
        for (int m = 0; m < Nn; m++) {
            float u = ss[m];
            cnt += (u > v) || ((u == v) && (m < tid));
        }
        if (cnt < k) { topi[b * k + cnt] = tid; topv[b * k + cnt] = v; }
    }
}

__device__ __forceinline__ void gather_body(const float* __restrict__ Hf,
                                            const float* __restrict__ G,
                                            const int* __restrict__ topi,
                                            const float* __restrict__ topv,
                                            float* __restrict__ Hg,
                                            float* __restrict__ Gr, int Nn, int k) {
    int b = blockIdx.x / k;
    int rr = blockIdx.x - b * k;
    int tid = threadIdx.x;
    int src = topi[b * k + rr];
    float gate = sigf(topv[b * k + rr]);
    Hg[(b * k + rr) * FF + tid] = Hf[(b * Nn + src) * FF + tid] * gate;
    for (int q = tid; q < k; q += 192)
        Gr[(b * k + rr) * k + q] = G[(b * Nn + src) * Nn + topi[b * k + q]];
}

// ---------------- wrappers ---------------------------------------------------
__global__ void ne1_kernel(const float* __restrict__ x, const float* __restrict__ W1) {
    ne_body(x, W1, d_Ne1, TT);
}
__global__ void ne2_kernel(const float* __restrict__ W2) {
    ne_body(d_Hg1, W2, d_Ne2, FF);
}
__global__ void rowcol1_kernel() { rowcol_body(d_G, d_row1, d_col1, NN); }
__global__ void rowcol2_kernel() { rowcol_body(d_G1, d_row2, d_col2, K1); }
__global__ void mp1_kernel() { mp_body(d_G, d_Ne1, d_M1, d_P1, NN); }
__global__ void mp2_kernel() { mp_body(d_G1, d_Ne2, d_M2, d_P2, K1); }
__global__ void hcat1_kernel() { hcat_body(d_G, d_M1, d_P1, d_row1, d_col1, d_H1, NN); }
__global__ void hcat2_kernel() { hcat_body(d_G1, d_M2, d_P2, d_row2, d_col2, d_H2, K1); }
__global__ void topk1_kernel(const float* __restrict__ w) {
    topk_body(d_H1, w, d_topv1, d_topi1, NN, K1);
}
__global__ void topk2_kernel(const float* __restrict__ w) {
    topk_body(d_H2, w, d_topv2, d_topi2, K1, K2);
}
__global__ void gather1_kernel() {
    gather_body(d_H1, d_G, d_topi1, d_topv1, d_Hg1, d_G1, NN, K1);
}

// final: gather2 + (B, 20*192) @ W_out + b_out, softmax over 2 classes
__global__ void final_kernel(const float* __restrict__ W_out,
                             const float* __restrict__ b_out,
                             float* __restrict__ out) {
    __shared__ float s0[256], s1[256];
    __shared__ int   sti[K2];
    __shared__ float sgate[K2];
    int b = blockIdx.x, tid = threadIdx.x;
    if (tid < K2) {
        sti[tid] = d_topi2[b * K2 + tid];
        sgate[tid] = sigf(d_topv2[b * K2 + tid]);
    }
    __syncthreads();
    float a0 = 0.0f, a1 = 0.0f;
    for (int f = tid; f < K2 * FF; f += 256) {
        int rr = f / FF, ff = f - rr * FF;
        float hv = d_H2[(b * K1 + sti[rr]) * FF + ff] * sgate[rr];
        a0 = fmaf(hv, W_out[f * 2 + 0], a0);
        a1 = fmaf(hv, W_out[f * 2 + 1], a1);
    }
    s0[tid] = a0; s1[tid] = a1;
    __syncthreads();
    for (int st = 128; st > 0; st >>= 1) {
        if (tid < st) { s0[tid] += s0[tid + st]; s1[tid] += s1[tid + st]; }
        __syncthreads();
    }
    if (tid == 0) {
        float l0 = s0[0] + b_out[0];
        float l1 = s1[0] + b_out[1];
        float m = fmaxf(l0, l1);
        float e0 = expf(l0 - m), e1 = expf(l1 - m);
        float inv = 1.0f / (e0 + e1);
        out[b * 2 + 0] = e0 * inv;
        out[b * 2 + 1] = e1 * inv;
    }
}

// ---------------- launch -----------------------------------------------------
extern "C" void kernel_launch(void* const* d_in, const int* in_sizes, int n_in,
                              void* d_out, int out_size) {
    (void)in_sizes; (void)n_in; (void)out_size;
    const float* x     = (const float*)d_in[0];
    const float* W_ih  = (const float*)d_in[1];
    const float* b_ih  = (const float*)d_in[2];
    const float* b_hh  = (const float*)d_in[3];
    const float* W_fc  = (const float*)d_in[4];
    const float* b_fc  = (const float*)d_in[5];
    const float* W1    = (const float*)d_in[6];
    const float* W2    = (const float*)d_in[7];
    const float* w1    = (const float*)d_in[8];
    const float* w2    = (const float*)d_in[9];
    const float* W_out = (const float*)d_in[10];
    const float* b_out = (const float*)d_in[11];
    float* out = (float*)d_out;

    lstm_kernel<<<BB * NN, 256>>>(x, W_ih, b_ih, b_hh);
    gmat_kernel<<<NN, 192>>>(W_fc, b_fc);
    ne1_kernel<<<BB * NN, 64>>>(x, W1);
    rowcol1_kernel<<<BB, 192>>>();
    mp1_kernel<<<BB * (NN / 4), 64>>>();
    hcat1_kernel<<<BB * (NN / 4), 64>>>();
    topk1_kernel<<<BB, 192>>>(w1);
    gather1_kernel<<<BB * K1, 192>>>();
    ne2_kernel<<<BB * K1, 64>>>(W2);
    rowcol2_kernel<<<BB, 192>>>();
    mp2_kernel<<<BB * (K1 / 4), 64>>>();
    hcat2_kernel<<<BB * (K1 / 4), 64>>>();
    topk2_kernel<<<BB, 192>>>(w2);
    final_kernel<<<BB, 256>>>(W_out, b_out, out);
}

// round 3
// speedup vs baseline: 1.1787x; 1.1787x over previous
#include <cuda_runtime.h>
#include <math.h>

// Problem constants (B=8, N=180, T=256, L=16, H=64, S=240)
#define BB  8
#define NN  180
#define TT  256
#define LL  16
#define HH  64
#define SSW 240
#define K1  60
#define K2  20
#define FF  192

// ---------------- scratch (__device__ globals; no allocation) ----------------
__device__ float d_hs[BB*NN*HH];
__device__ float d_r[BB*NN];
__device__ float d_G [BB*NN*NN];    // G[b,j,n]
__device__ float d_Gt[BB*NN*NN];    // Gt[b,n,j] = G[b,j,n]
__device__ float d_Ne1[BB*NN*HH];
__device__ float d_row1[BB*NN];
__device__ float d_col1[BB*NN];
__device__ float d_M1[BB*NN*HH];
__device__ float d_P1[BB*NN*HH];
__device__ float d_H1[BB*NN*FF];
__device__ float d_topv1[BB*K1];
__device__ int   d_topi1[BB*K1];
__device__ float d_G1 [BB*K1*K1];
__device__ float d_Gt1[BB*K1*K1];
__device__ float d_Ne2[BB*K1*HH];
__device__ float d_row2[BB*K1];
__device__ float d_col2[BB*K1];
__device__ float d_M2[BB*K1*HH];
__device__ float d_P2[BB*K1*HH];
__device__ float d_H2[BB*K1*FF];

__device__ __forceinline__ float sigf(float x) {
    return __fdividef(1.0f, 1.0f + __expf(-x));
}
__device__ __forceinline__ float tanh_f(float x) {
    return 1.0f - __fdividef(2.0f, __expf(2.0f * x) + 1.0f);
}

// ---------------- K1: windowed LSTM-cell reduction (unchanged math) ---------
__global__ void lstm_kernel(const float* __restrict__ x,
                            const float* __restrict__ W_ih,
                            const float* __restrict__ b_ih,
                            const float* __restrict__ b_hh) {
    int n = blockIdx.x >> 3;
    int b = blockIdx.x & 7;
    __shared__ float sx[TT];
    __shared__ float sinv[SSW + 16];
    __shared__ float sp[256];

    int tid = threadIdx.x;
    const float* xp = x + (b * NN + n) * TT;
    sx[tid] = xp[tid];
    if (tid < 16) sinv[SSW + tid] = 0.0f;
    __syncthreads();
    if (tid < SSW) sinv[tid] = __fdividef(1.0f, sx[LL + tid]);

    int h = tid & 63;
    const float* Wn = W_ih + n * 256 * LL;
    float w0[LL], w1[LL], w2[LL];
#pragma unroll
    for (int l = 0; l < LL; l++) {
        w0[l] = Wn[h * LL + l];
        w1[l] = Wn[(128 + h) * LL + l];
        w2[l] = Wn[(192 + h) * LL + l];
    }
    float bi0 = b_ih[n * 256 + h]       + b_hh[n * 256 + h];
    float bi1 = b_ih[n * 256 + 128 + h] + b_hh[n * 256 + 128 + h];
    float bi2 = b_ih[n * 256 + 192 + h] + b_hh[n * 256 + 192 + h];
    __syncthreads();

    float acc = 0.0f;
    int s0 = tid >> 6;
    for (int i = 0; i < SSW / 4; i++) {
        int s = s0 + 4 * i;
        float ig = bi0, gg = bi1, og = bi2;
#pragma unroll
        for (int l = 0; l < LL; l++) {
            float xv = sx[s + l];
            ig = fmaf(w0[l], xv, ig);
            gg = fmaf(w1[l], xv, gg);
            og = fmaf(w2[l], xv, og);
        }
        float c  = sigf(ig) * tanh_f(gg);
        float hv = sigf(og) * tanh_f(c);
        acc = fmaf(hv, sinv[s], acc);
    }
    sp[tid] = acc;
    __syncthreads();
    if (tid < HH)
        d_hs[(b * NN + n) * HH + tid] = sp[tid] + sp[tid + 64] + sp[tid + 128] + sp[tid + 192];
    if (tid < 128) sp[tid] = sinv[tid] + sinv[tid + 128];
    __syncthreads();
    if (tid < 64) sp[tid] += sp[tid + 64];
    __syncthreads();
    if (tid < 32) {
        float v = sp[tid] + sp[tid + 32];
#pragma unroll
        for (int off = 16; off > 0; off >>= 1)
            v += __shfl_down_sync(0xffffffffu, v, off);
        if (tid == 0) d_r[b * NN + n] = v;
    }
}

// ---------------- K2: G + Gt ------------------------------------------------
__global__ void gmat_kernel(const float* __restrict__ W_fc,
                            const float* __restrict__ b_fc) {
    int n = blockIdx.x;
    __shared__ float sh[BB * HH];
    __shared__ float srr[BB];
    int tid = threadIdx.x;   // 192
    for (int t = tid; t < BB * HH; t += 192) {
        int b = t >> 6;
        sh[t] = d_hs[(b * NN + n) * HH + (t & 63)];
    }
    if (tid < BB) srr[tid] = d_r[tid * NN + n];
    __syncthreads();

    if (tid < NN) {
        int j = tid;
        const float4* w = (const float4*)(W_fc + (n * NN + j) * HH);
        float bfc = b_fc[n * NN + j];
        float acc[BB];
#pragma unroll
        for (int b = 0; b < BB; b++) acc[b] = bfc * srr[b];
#pragma unroll
        for (int h4 = 0; h4 < HH / 4; h4++) {
            float4 wv = w[h4];
#pragma unroll
            for (int b = 0; b < BB; b++) {
                const float* shb = sh + b * HH + h4 * 4;
                acc[b] = fmaf(wv.x, shb[0], acc[b]);
                acc[b] = fmaf(wv.y, shb[1], acc[b]);
                acc[b] = fmaf(wv.z, shb[2], acc[b]);
                acc[b] = fmaf(wv.w, shb[3], acc[b]);
            }
        }
#pragma unroll
        for (int b = 0; b < BB; b++) {
            float g = acc[b] * (1.0f / (float)SSW);
            d_G [(b * NN + j) * NN + n] = g;
            d_Gt[(b * NN + n) * NN + j] = g;
        }
    }
}

// ---------------- Ne1 = x @ W1; 8 rows / block ------------------------------
__global__ void ne1_kernel(const float* __restrict__ x, const float* __restrict__ W1) {
    __shared__ float sx[8 * TT];
    int bn0 = blockIdx.x * 8;
    int tid = threadIdx.x;   // 256
    const float* xp = x + bn0 * TT;
    for (int idx = tid; idx < 8 * TT; idx += 256) sx[idx] = xp[idx];
    __syncthreads();
    int o = tid & 63, g = tid >> 6;          // g in 0..3 -> rows 2g, 2g+1
    float a0 = 0.0f, a1 = 0.0f;
    const float* s0 = sx + (2 * g) * TT;
    const float* s1 = sx + (2 * g + 1) * TT;
    for (int k = 0; k < TT; k++) {
        float w = W1[k * HH + o];
        a0 = fmaf(w, s0[k], a0);
        a1 = fmaf(w, s1[k], a1);
    }
    d_Ne1[(bn0 + 2 * g) * HH + o]     = a0;
    d_Ne1[(bn0 + 2 * g + 1) * HH + o] = a1;
}

// ---------------- mp: M=G@Ne, P=Gt@Ne, plus row/col sums --------------------
// Block: 256 threads, one b, 4 rows. k-split 4 ways.
__device__ __forceinline__ void mp_body(const float* __restrict__ G,
                                        const float* __restrict__ Gt,
                                        const float* __restrict__ Ne,
                                        float* __restrict__ M,
                                        float* __restrict__ P,
                                        float* __restrict__ row,
                                        float* __restrict__ col, int Nn) {
    __shared__ float sG [4][NN];
    __shared__ float sGt[4][NN];
    __shared__ float red[4][4][HH];
    int nt = Nn / 4;
    int b  = blockIdx.x / nt;
    int it = (blockIdx.x - b * nt) * 4;
    int tid = threadIdx.x;
    int o = tid & 63, q = tid >> 6;
    int chunk = Nn / 4;

    for (int idx = tid; idx < 4 * Nn; idx += 256) {
        int ii = idx / Nn, k = idx - ii * Nn;
        sG [ii][k] = G [(b * Nn + it + ii) * Nn + k];
        sGt[ii][k] = Gt[(b * Nn + it + ii) * Nn + k];
    }
    __syncthreads();

    // row/col sums: 8 warps, warp w -> (ii = w&3, kind = w>>2)
    {
        int w = tid >> 5, lane = tid & 31;
        int ii = w & 3, kind = w >> 2;
        float t = 0.0f;
        const float (*tile)[NN] = kind ? sGt : sG;
        for (int k = lane; k < Nn; k += 32) t += tile[ii][k];
#pragma unroll
        for (int off = 16; off > 0; off >>= 1)
            t += __shfl_down_sync(0xffffffffu, t, off);
        if (lane == 0) {
            if (kind == 0) row[b * Nn + it + ii] = t;
            else           col[b * Nn + it + ii] = t;
        }
    }

    float m[4] = {0, 0, 0, 0}, p[4] = {0, 0, 0, 0};
    for (int k = q * chunk; k < (q + 1) * chunk; k++) {
        float ne = Ne[(b * Nn + k) * HH + o];
#pragma unroll
        for (int ii = 0; ii < 4; ii++) {
            m[ii] = fmaf(sG [ii][k], ne, m[ii]);
            p[ii] = fmaf(sGt[ii][k], ne, p[ii]);
        }
    }
#pragma unroll
    for (int ii = 0; ii < 4; ii++) red[q][ii][o] = m[ii];
    __syncthreads();
    {
        float s = red[0][q][o] + red[1][q][o] + red[2][q][o] + red[3][q][o];
        M[(b * Nn + it + q) * HH + o] = s;
    }
    __syncthreads();
#pragma unroll
    for (int ii = 0; ii < 4; ii++) red[q][ii][o] = p[ii];
    __syncthreads();
    {
        float s = red[0][q][o] + red[1][q][o] + red[2][q][o] + red[3][q][o];
        P[(b * Nn + it + q) * HH + o] = s;
    }
}

// ---------------- hcat ------------------------------------------------------
__device__ __forceinline__ void hcat_body(const float* __restrict__ G,
                                          const float* __restrict__ Gt,
                                          const float* __restrict__ M,
                                          const float* __restrict__ P,
                                          const float* __restrict__ row,
                                          const float* __restrict__ col,
                                          float* __restrict__ Hout, int Nn) {
    __shared__ float sG [4][NN];
    __shared__ float sGt[4][NN];
    __shared__ float sir[NN];
    __shared__ float sic[NN];
    __shared__ float red[4][4][HH];
    int nt = Nn / 4;
    int b  = blockIdx.x / nt;
    int it = (blockIdx.x - b * nt) * 4;
    int tid = threadIdx.x;
    int o = tid & 63, q = tid >> 6;
    int chunk = Nn / 4;

    for (int k = tid; k < Nn; k += 256) {
        sir[k] = __fdividef(1.0f, row[b * Nn + k]);
        sic[k] = __fdividef(1.0f, col[b * Nn + k]);
    }
    for (int idx = tid; idx < 4 * Nn; idx += 256) {
        int ii = idx / Nn, k = idx - ii * Nn;
        sG [ii][k] = G [(b * Nn + it + ii) * Nn + k];
        sGt[ii][k] = Gt[(b * Nn + it + ii) * Nn + k];
    }
    __syncthreads();

    float a2[4] = {0, 0, 0, 0}, a3[4] = {0, 0, 0, 0};
    for (int k = q * chunk; k < (q + 1) * chunk; k++) {
        float mv = M[(b * Nn + k) * HH + o] * sir[k];
        float pv = P[(b * Nn + k) * HH + o] * sic[k];
#pragma unroll
        for (int ii = 0; ii < 4; ii++) {
            a2[ii] = fmaf(sGt[ii][k], mv, a2[ii]);
            a3[ii] = fmaf(sG [ii][k], pv, a3[ii]);
        }
    }
#pragma unroll
    for (int ii = 0; ii < 4; ii++) red[q][ii][o] = a2[ii];
    __syncthreads();
    {
        float s = red[0][q][o] + red[1][q][o] + red[2][q][o] + red[3][q][o];
        Hout[(b * Nn + it + q) * FF + HH + o] = fmaxf(0.0f, s);
    }
    __syncthreads();
#pragma unroll
    for (int ii = 0; ii < 4; ii++) red[q][ii][o] = a3[ii];
    __syncthreads();
    {
        float s = red[0][q][o] + red[1][q][o] + red[2][q][o] + red[3][q][o];
        Hout[(b * Nn + it + q) * FF + 2 * HH + o] = fmaxf(0.0f, s);
        int i = it + q;
        float m0 = M[(b * Nn + i) * HH + o];
        float p0 = P[(b * Nn + i) * HH + o];
        Hout[(b * Nn + i) * FF + o] = fmaxf(0.0f, 0.5f * (m0 + p0));
    }
}

__global__ void mp1_kernel()   { mp_body(d_G, d_Gt, d_Ne1, d_M1, d_P1, d_row1, d_col1, NN); }
__global__ void mp2_kernel()   { mp_body(d_G1, d_Gt1, d_Ne2, d_M2, d_P2, d_row2, d_col2, K1); }
__global__ void hcat1_kernel() { hcat_body(d_G, d_Gt, d_M1, d_P1, d_row1, d_col1, d_H1, NN); }
__global__ void hcat2_kernel() { hcat_body(d_G1, d_Gt1, d_M2, d_P2, d_row2, d_col2, d_H2, K1); }

// ---------------- topk1: warp-cooperative scores + rank count ---------------
__global__ void topk1_kernel(const float* __restrict__ w) {
    __shared__ float ss[NN];
    __shared__ float sw[FF];
    __shared__ float rtmp[256];
    __shared__ float srn;
    int b = blockIdx.x, tid = threadIdx.x;   // 256
    rtmp[tid] = 0.0f;
    if (tid < FF) { float v = w[tid]; sw[tid] = v; rtmp[tid] = v * v; }
    __syncthreads();
    for (int st = 128; st > 32; st >>= 1) {
        if (tid < st) rtmp[tid] += rtmp[tid + st];
        __syncthreads();
    }
    if (tid < 32) {
        float v = rtmp[tid] + rtmp[tid + 32];
#pragma unroll
        for (int off = 16; off > 0; off >>= 1)
            v += __shfl_down_sync(0xffffffffu, v, off);
        if (tid == 0) srn = rsqrtf(v);
    }
    __syncthreads();

    int wrp = tid >> 5, lane = tid & 31;
    for (int n = wrp; n < NN; n += 8) {
        const float* hp = d_H1 + (b * NN + n) * FF;
        float acc = 0.0f;
        for (int f = lane; f < FF; f += 32) acc = fmaf(hp[f], sw[f], acc);
#pragma unroll
        for (int off = 16; off > 0; off >>= 1)
            acc += __shfl_down_sync(0xffffffffu, acc, off);
        if (lane == 0) ss[n] = acc * srn;
    }
    __syncthreads();
    if (tid < NN) {
        float v = ss[tid];
        int cnt = 0;
        for (int m = 0; m < NN; m++) {
            float u = ss[m];
            cnt += (u > v) || ((u == v) && (m < tid));
        }
        if (cnt < K1) { d_topi1[b * K1 + cnt] = tid; d_topv1[b * K1 + cnt] = v; }
    }
}

// ---------------- gather (G1, Gt1) + Ne2 ------------------------------------
__global__ void gather_ne2_kernel(const float* __restrict__ W2) {
    __shared__ int   sti[K1];
    __shared__ float shg[FF];
    __shared__ float red[3][HH];
    int b = blockIdx.x / K1;
    int rr = blockIdx.x - b * K1;
    int tid = threadIdx.x;   // 192
    if (tid < K1) sti[tid] = d_topi1[b * K1 + tid];
    int src = d_topi1[b * K1 + rr];
    float gate = sigf(d_topv1[b * K1 + rr]);
    shg[tid] = d_H1[(b * NN + src) * FF + tid] * gate;
    __syncthreads();
    if (tid < K1) {
        d_G1 [(b * K1 + rr) * K1 + tid] = d_G [(b * NN + src) * NN + sti[tid]];
        d_Gt1[(b * K1 + rr) * K1 + tid] = d_Gt[(b * NN + src) * NN + sti[tid]];
    }
    int o = tid & 63, g = tid >> 6;  // g in 0..2, k-chunks of 64
    float acc = 0.0f;
    for (int f = g * 64; f < (g + 1) * 64; f++)
        acc = fmaf(shg[f], W2[f * HH + o], acc);
    red[g][o] = acc;
    __syncthreads();
    if (tid < HH)
        d_Ne2[(b * K1 + rr) * HH + tid] = red[0][tid] + red[1][tid] + red[2][tid];
}

// ---------------- topk2 + final output --------------------------------------
__global__ void topk2_final_kernel(const float* __restrict__ w,
                                   const float* __restrict__ W_out,
                                   const float* __restrict__ b_out,
                                   float* __restrict__ out) {
    __shared__ float ss[K1];
    __shared__ float sw[FF];
    __shared__ float rtmp[256];
    __shared__ float s1buf[256];
    __shared__ float srn;
    __shared__ int   sti2[K2];
    __shared__ float sgate[K2];
    int b = blockIdx.x, tid = threadIdx.x;  // 256
    rtmp[tid] = 0.0f;
    if (tid < FF) { float v = w[tid]; sw[tid] = v; rtmp[tid] = v * v; }
    __syncthreads();
    for (int st = 128; st > 32; st >>= 1) {
        if (tid < st) rtmp[tid] += rtmp[tid + st];
        __syncthreads();
    }
    if (tid < 32) {
        float v = rtmp[tid] + rtmp[tid + 32];
#pragma unroll
        for (int off = 16; off > 0; off >>= 1)
            v += __shfl_down_sync(0xffffffffu, v, off);
        if (tid == 0) srn = rsqrtf(v);
    }
    __syncthreads();

    int wrp = tid >> 5, lane = tid & 31;
    for (int n = wrp; n < K1; n += 8) {
        const float* hp = d_H2 + (b * K1 + n) * FF;
        float acc = 0.0f;
        for (int f = lane; f < FF; f += 32) acc = fmaf(hp[f], sw[f], acc);
#pragma unroll
        for (int off = 16; off > 0; off >>= 1)
            acc += __shfl_down_sync(0xffffffffu, acc, off);
        if (lane == 0) ss[n] = acc * srn;
    }
    __syncthreads();
    if (tid < K1) {
        float v = ss[tid];
        int cnt = 0;
        for (int m = 0; m < K1; m++) {
            float u = ss[m];
            cnt += (u > v) || ((u == v) && (m < tid));
        }
        if (cnt < K2) { sti2[cnt] = tid; sgate[cnt] = sigf(v); }
    }
    __syncthreads();

    float a0 = 0.0f, a1 = 0.0f;
    const float2* Wo = (const float2*)W_out;
    for (int f = tid; f < K2 * FF; f += 256) {
        int rr = f / FF, ff = f - rr * FF;
        float hv = d_H2[(b * K1 + sti2[rr]) * FF + ff] * sgate[rr];
        float2 wv = Wo[f];
        a0 = fmaf(hv, wv.x, a0);
        a1 = fmaf(hv, wv.y, a1);
    }
    rtmp[tid] = a0; s1buf[tid] = a1;
    __syncthreads();
    for (int st = 128; st > 0; st >>= 1) {
        if (tid < st) { rtmp[tid] += rtmp[tid + st]; s1buf[tid] += s1buf[tid + st]; }
        __syncthreads();
    }
    if (tid == 0) {
        float l0 = rtmp[0] + b_out[0];
        float l1 = s1buf[0] + b_out[1];
        float m = fmaxf(l0, l1);
        float e0 = expf(l0 - m), e1 = expf(l1 - m);
        float inv = 1.0f / (e0 + e1);
        out[b * 2 + 0] = e0 * inv;
        out[b * 2 + 1] = e1 * inv;
    }
}

// ---------------- launch -----------------------------------------------------
extern "C" void kernel_launch(void* const* d_in, const int* in_sizes, int n_in,
                              void* d_out, int out_size) {
    (void)in_sizes; (void)n_in; (void)out_size;
    const float* x     = (const float*)d_in[0];
    const float* W_ih  = (const float*)d_in[1];
    const float* b_ih  = (const float*)d_in[2];
    const float* b_hh  = (const float*)d_in[3];
    const float* W_fc  = (const float*)d_in[4];
    const float* b_fc  = (const float*)d_in[5];
    const float* W1    = (const float*)d_in[6];
    const float* W2    = (const float*)d_in[7];
    const float* w1    = (const float*)d_in[8];
    const float* w2    = (const float*)d_in[9];
    const float* W_out = (const float*)d_in[10];
    const float* b_out = (const float*)d_in[11];
    float* out = (float*)d_out;

    lstm_kernel<<<BB * NN, 256>>>(x, W_ih, b_ih, b_hh);
    gmat_kernel<<<NN, 192>>>(W_fc, b_fc);
    ne1_kernel<<<BB * NN / 8, 256>>>(x, W1);
    mp1_kernel<<<BB * (NN / 4), 256>>>();
    hcat1_kernel<<<BB * (NN / 4), 256>>>();
    topk1_kernel<<<BB, 256>>>(w1);
    gather_ne2_kernel<<<BB * K1, 192>>>(W2);
    mp2_kernel<<<BB * (K1 / 4), 256>>>();
    hcat2_kernel<<<BB * (K1 / 4), 256>>>();
    topk2_final_kernel<<<BB, 256>>>(w2, W_out, b_out, out);
}